// round 5
// baseline (speedup 1.0000x reference)
#include <cuda_runtime.h>
#include <cstdint>

#define B_SZ 512
#define IN_F 512
#define OUT_F 100
#define KD 5
#define OC 500              // OUT_F * KD
#define LOG2E 1.4426950408889634f
#define NT 32               // number of batch tiles
#define TS 16               // tile size (NT*TS = B_SZ)

// Scratch for M = (x @ T) * log2(e), laid out [b][o*5+k], 512x500 floats = 1MB
__device__ float g_M[B_SZ * OC];

__device__ __forceinline__ float ex2(float x) {
    float r;
    asm("ex2.approx.f32 %0, %1;" : "=f"(r) : "f"(x));
    return r;
}

__device__ __forceinline__ unsigned long long add2(unsigned long long a,
                                                   unsigned long long b) {
    unsigned long long d;
    asm("add.rn.f32x2 %0, %1, %2;" : "=l"(d) : "l"(a), "l"(b));
    return d;
}

__device__ __forceinline__ void fma2(unsigned long long& acc,
                                     unsigned long long a,
                                     unsigned long long b) {
    asm("fma.rn.f32x2 %0, %1, %2, %0;" : "+l"(acc) : "l"(a), "l"(b));
}

__device__ __forceinline__ unsigned long long pack2(float lo, float hi) {
    unsigned long long d;
    asm("mov.b64 %0, {%1, %2};" : "=l"(d) : "f"(lo), "f"(hi));
    return d;
}

__device__ __forceinline__ void unpack2(float& lo, float& hi, unsigned long long v) {
    asm("mov.b64 {%0, %1}, %2;" : "=f"(lo), "=f"(hi) : "l"(v));
}

// ---------------------------------------------------------------------------
// Kernel 1: M[b][oc] = sum_i x[b][i] * T[i][oc], scaled by log2e. FFMA2 path.
// Block 512 threads: lane = t>>2 (oc), kh = t&3 (in-warp K-split of 128).
// Thread owns 1 oc x 16 b-rows = 8 packed f32x2 accumulators. xs is [i][bb]
// so ulonglong2 LDS.128 yields pre-packed (bb, bb+1) pairs. kh-reduction via
// 2 rounds of 64-bit shfl.bfly (lanes 1,2) — no reduction smem.
// Grid (32, 4) = 128 blocks x 16 warps. Also zeroes `out` (blockIdx.y == 0).
// ---------------------------------------------------------------------------
__global__ void __launch_bounds__(512) gemm_kernel(const float* __restrict__ x,
                                                   const float* __restrict__ T,
                                                   float* __restrict__ out) {
    __shared__ __align__(16) float xs[IN_F * 16];   // [i][bb], 32KB

    const int t = threadIdx.x;
    const int lane = t >> 2;               // 0..127  (oc lane)
    const int kh = t & 3;                  // 0..3    (K-slice, in-warp)
    const int b0 = blockIdx.x * 16;
    const int oc = blockIdx.y * 128 + lane;
    const bool ocv = (oc < OC);

    if (blockIdx.y == 0) {
        for (int idx = blockIdx.x * 512 + t; idx < B_SZ * OUT_F; idx += 32 * 512)
            out[idx] = 0.0f;
    }

    // cooperative transpose load: x[b0+bb][i] -> xs[i*16+bb]
    for (int idx = t; idx < IN_F * 16; idx += 512) {
        int bb = idx >> 9;                 // 0..15
        int i = idx & (IN_F - 1);          // 0..511
        xs[i * 16 + bb] = x[(b0 + bb) * IN_F + i];
    }
    __syncthreads();

    unsigned long long acc[8] = {0ull, 0ull, 0ull, 0ull, 0ull, 0ull, 0ull, 0ull};

    if (ocv) {
        const float* tp = T + (size_t)(kh * 128) * OC + oc;
        const float* xbase = xs + kh * 128 * 16;
#pragma unroll 8
        for (int i = 0; i < 128; i++) {
            float tv = tp[i * OC];
            unsigned long long tvtv = pack2(tv, tv);
            const ulonglong2* row = reinterpret_cast<const ulonglong2*>(xbase + i * 16);
            ulonglong2 v0 = row[0];
            ulonglong2 v1 = row[1];
            fma2(acc[0], v0.x, tvtv);
            fma2(acc[1], v0.y, tvtv);
            fma2(acc[2], v1.x, tvtv);
            fma2(acc[3], v1.y, tvtv);
            ulonglong2 v2 = row[2];
            ulonglong2 v3 = row[3];
            fma2(acc[4], v2.x, tvtv);
            fma2(acc[5], v2.y, tvtv);
            fma2(acc[6], v3.x, tvtv);
            fma2(acc[7], v3.y, tvtv);
        }
    }

    // reduce the 4 kh-slices (lanes xor 1, xor 2 within each 4-lane group)
#pragma unroll
    for (int p = 0; p < 8; p++) {
        acc[p] = add2(acc[p], __shfl_xor_sync(0xffffffffu, acc[p], 1));
        acc[p] = add2(acc[p], __shfl_xor_sync(0xffffffffu, acc[p], 2));
    }

    if (kh == 0 && ocv) {
#pragma unroll
        for (int p = 0; p < 8; p++) {
            float lo, hi;
            unpack2(lo, hi, acc[p]);
            g_M[(size_t)(b0 + 2 * p + 0) * OC + oc] = lo * LOG2E;
            g_M[(size_t)(b0 + 2 * p + 1) * OC + oc] = hi * LOG2E;
        }
    }
}

// ---------------------------------------------------------------------------
// Kernel 2 (symmetric, packed f32x2): one block per unordered tile pair
// (ta <= tb), 32 tiles of 16 rows -> 528 blocks. Block 416 threads; t<400:
// o = t>>2, jl = t&3, 4 j-rows per thread. j-side rows stored NEGATED and
// packed (k0,k1) / (k2,k3) so |d-a| = AND(add2(d, na), signmask): subs and
// sums on the fma pipe (halved op count), abs on the idle ALU pipe.
// ---------------------------------------------------------------------------
__global__ void __launch_bounds__(416, 2) md_kernel(float* __restrict__ out) {
    __shared__ __align__(16) float ms[TS * OC];  // 32KB

    // decode blockIdx.x -> (ta, tb), upper triangle row-major
    int rem = blockIdx.x;
    int ta = 0;
    while (rem >= NT - ta) { rem -= NT - ta; ta++; }
    const int tb = ta + rem;
    const bool diag = (ta == tb);

    const int t = threadIdx.x;
    const bool act = (t < 400);
    const int o = act ? (t >> 2) : 99;   // clamp for safe reads
    const int jl = t & 3;

    // stage tile_a: 16 rows x 500 floats = 2000 float4
    {
        const float4* src = reinterpret_cast<const float4*>(g_M + (size_t)ta * TS * OC);
        float4* dst = reinterpret_cast<float4*>(ms);
        for (int i = t; i < 2000; i += 416) dst[i] = src[i];
    }

    // load j-side rows, negate, pack
    unsigned long long na01[4], na23[4];
    float na4[4];
    float accJ[4];
#pragma unroll
    for (int r = 0; r < 4; r++) {
        const int j = tb * TS + jl + 4 * r;       // < 512 always
        const float* m = g_M + (size_t)j * OC + o * KD;
        na01[r] = pack2(-m[0], -m[1]);
        na23[r] = pack2(-m[2], -m[3]);
        na4[r] = -m[4];
        accJ[r] = 0.f;
    }
    __syncthreads();

    const unsigned long long SMASK = 0x7FFFFFFF7FFFFFFFull;

#pragma unroll
    for (int ii = 0; ii < TS; ii++) {
        const float* m = ms + ii * OC + o * KD;  // stride-5: conflict-free
        float d0 = m[0], d1 = m[1], d2 = m[2], d3 = m[3], d4 = m[4];
        unsigned long long d01 = pack2(d0, d1);
        unsigned long long d23 = pack2(d2, d3);
        float loc = 0.f;
#pragma unroll
        for (int r = 0; r < 4; r++) {
            unsigned long long s01 = add2(d01, na01[r]) & SMASK;  // |d-a| pairs
            unsigned long long s23 = add2(d23, na23[r]) & SMASK;
            unsigned long long s = add2(s01, s23);
            float lo, hi;
            unpack2(lo, hi, s);
            float e4 = d4 + na4[r];
            float n = (-lo - hi) - fabsf(e4);
            float e = ex2(n);
            accJ[r] += e;
            loc += e;
        }
        if (!diag) {
            loc += __shfl_xor_sync(0xffffffffu, loc, 1);
            loc += __shfl_xor_sync(0xffffffffu, loc, 2);
            if (act && jl == 0)
                atomicAdd(&out[(ta * TS + ii) * OUT_F + o], loc);
        }
    }

    if (act) {
#pragma unroll
        for (int r = 0; r < 4; r++) {
            float v = accJ[r] - (diag ? 1.0f : 0.0f);
            atomicAdd(&out[(tb * TS + jl + 4 * r) * OUT_F + o], v);
        }
    }
}

extern "C" void kernel_launch(void* const* d_in, const int* in_sizes, int n_in,
                              void* d_out, int out_size) {
    const float* x = (const float*)d_in[0];   // [512, 512]
    const float* T = (const float*)d_in[1];   // [512, 100, 5] -> [512, 500]
    float* out = (float*)d_out;               // [512, 100]

    gemm_kernel<<<dim3(32, 4), 512>>>(x, T, out);
    md_kernel<<<NT * (NT + 1) / 2, 416>>>(out);  // 528 blocks
}

// round 6
// speedup vs baseline: 3.0374x; 3.0374x over previous
#include <cuda_runtime.h>
#include <cstdint>

#define B_SZ 512
#define IN_F 512
#define OUT_F 100
#define KD 5
#define OC 500              // OUT_F * KD
#define LOG2E 1.4426950408889634f
#define NT 32               // number of batch tiles
#define TS 16               // tile size (NT*TS = B_SZ)
#define NP 528              // NT*(NT+1)/2 unordered tile pairs
#define MD_BLOCKS 264       // 2 pairs per block -> single wave at occ 2

// Scratch for M = (x @ T) * log2(e), laid out [b][o*5+k], 512x500 floats = 1MB
__device__ float g_M[B_SZ * OC];

__device__ __forceinline__ float ex2(float x) {
    float r;
    asm("ex2.approx.f32 %0, %1;" : "=f"(r) : "f"(x));
    return r;
}

// ---------------------------------------------------------------------------
// Kernel 1: M[b][oc] = sum_i x[b][i] * T[i][oc], scaled by log2e.
// Block: 512 threads = 64 oc-pair-lanes x 8 K-slices (kh). Each thread owns
// 8 b-rows x 2 consecutive oc (float2 T loads) over a 64-long K-slice;
// slices reduced through smem. Grid (64, 4). Also zeroes `out`.
// ---------------------------------------------------------------------------
__global__ void __launch_bounds__(512) gemm_kernel(const float* __restrict__ x,
                                                   const float* __restrict__ T,
                                                   float* __restrict__ out) {
    __shared__ __align__(16) float xs[IN_F * 8];          // [i][bb], 16KB
    __shared__ __align__(16) float red[7 * 8 * 128];      // kh=1..7 partials, 28KB

    const int t = threadIdx.x;
    const int lane = t & 63;               // oc-pair lane
    const int kh = t >> 6;                 // 0..7
    const int b0 = blockIdx.x * 8;
    const int oc0 = blockIdx.y * 128;
    const int oc = oc0 + lane * 2;
    const bool ocv = (oc < OC);

    if (blockIdx.y == 0) {
        for (int idx = blockIdx.x * 512 + t; idx < B_SZ * OUT_F; idx += 64 * 512)
            out[idx] = 0.0f;
    }

    // cooperative transpose load: x[b0+bb][i] -> xs[i*8+bb]
    for (int idx = t; idx < IN_F * 8; idx += 512) {
        int bb = idx >> 9;
        int i = idx & (IN_F - 1);
        xs[i * 8 + bb] = x[(b0 + bb) * IN_F + i];
    }
    __syncthreads();

    float accx[8] = {0.f, 0.f, 0.f, 0.f, 0.f, 0.f, 0.f, 0.f};
    float accy[8] = {0.f, 0.f, 0.f, 0.f, 0.f, 0.f, 0.f, 0.f};

    if (ocv) {
        const float* tp = T + (size_t)(kh * 64) * OC + oc;
        const float* xp = xs + kh * 64 * 8;
#pragma unroll 8
        for (int i = 0; i < 64; i++) {
            float2 tv = *reinterpret_cast<const float2*>(tp + i * OC);
            float4 xa = *reinterpret_cast<const float4*>(xp + i * 8);
            float4 xb = *reinterpret_cast<const float4*>(xp + i * 8 + 4);
            accx[0] += xa.x * tv.x; accy[0] += xa.x * tv.y;
            accx[1] += xa.y * tv.x; accy[1] += xa.y * tv.y;
            accx[2] += xa.z * tv.x; accy[2] += xa.z * tv.y;
            accx[3] += xa.w * tv.x; accy[3] += xa.w * tv.y;
            accx[4] += xb.x * tv.x; accy[4] += xb.x * tv.y;
            accx[5] += xb.y * tv.x; accy[5] += xb.y * tv.y;
            accx[6] += xb.z * tv.x; accy[6] += xb.z * tv.y;
            accx[7] += xb.w * tv.x; accy[7] += xb.w * tv.y;
        }
    }

    if (kh > 0) {
        float* rp = red + (kh - 1) * 1024 + lane * 2;
#pragma unroll
        for (int bb = 0; bb < 8; bb++) {
            rp[bb * 128 + 0] = accx[bb];
            rp[bb * 128 + 1] = accy[bb];
        }
    }
    __syncthreads();
    if (kh == 0 && ocv) {
#pragma unroll
        for (int bb = 0; bb < 8; bb++) {
            float sx = accx[bb], sy = accy[bb];
#pragma unroll
            for (int s = 0; s < 7; s++) {
                sx += red[s * 1024 + bb * 128 + lane * 2 + 0];
                sy += red[s * 1024 + bb * 128 + lane * 2 + 1];
            }
            float2 o2;
            o2.x = sx * LOG2E;
            o2.y = sy * LOG2E;
            *reinterpret_cast<float2*>(&g_M[(size_t)(b0 + bb) * OC + oc]) = o2;
        }
    }
}

// ---------------------------------------------------------------------------
// Kernel 2 (symmetric, pair-fused): 264 blocks, each handling unordered tile
// pairs p = blockIdx.x and p + 264 sequentially. 264 blocks at occ-2 = one
// wave (296 slots) — no wave-quantization tail.
// Per pair: block 416 threads; t<400: o = t>>2, jl = t&3, 4 j-rows per
// thread in regs; 16 i-rows of tile_a staged in smem. e(i,j) -> accJ[r]
// (out[j]); transpose sum over j reduced across 4 jl-lanes via shfl.bfly
// -> atomicAdd out[i] (off-diagonal only). Diagonal subtracts self exp(0)=1.
// ---------------------------------------------------------------------------
__global__ void __launch_bounds__(416, 2) md_kernel(float* __restrict__ out) {
    __shared__ __align__(16) float ms[TS * OC];  // 32KB

    const int t = threadIdx.x;
    const bool act = (t < 400);
    const int o = act ? (t >> 2) : 99;   // clamp for safe reads
    const int jl = t & 3;

    for (int pp = 0; pp < 2; pp++) {
        const int p = blockIdx.x + pp * MD_BLOCKS;   // 0..527

        // decode p -> (ta, tb), upper triangle row-major
        int rem = p;
        int ta = 0;
        while (rem >= NT - ta) { rem -= NT - ta; ta++; }
        const int tb = ta + rem;
        const bool diag = (ta == tb);

        __syncthreads();   // protect ms reuse across pair iterations
        // stage tile_a: 16 rows x 500 floats = 2000 float4
        {
            const float4* src = reinterpret_cast<const float4*>(g_M + (size_t)ta * TS * OC);
            float4* dst = reinterpret_cast<float4*>(ms);
            for (int i = t; i < 2000; i += 416) dst[i] = src[i];
        }

        // load j-side rows into registers
        float a[4][5];
        float accJ[4];
#pragma unroll
        for (int r = 0; r < 4; r++) {
            const int j = tb * TS + jl + 4 * r;       // < 512 always
            const float* m = g_M + (size_t)j * OC + o * KD;
            a[r][0] = m[0]; a[r][1] = m[1]; a[r][2] = m[2];
            a[r][3] = m[3]; a[r][4] = m[4];
            accJ[r] = 0.f;
        }
        __syncthreads();

#pragma unroll
        for (int ii = 0; ii < TS; ii++) {
            const float* m = ms + ii * OC + o * KD;  // stride-5: conflict-free
            float d0 = m[0], d1 = m[1], d2 = m[2], d3 = m[3], d4 = m[4];
            float loc = 0.f;
#pragma unroll
            for (int r = 0; r < 4; r++) {
                float pa = -fabsf(d0 - a[r][0]) - fabsf(d1 - a[r][1]);
                float qa = -fabsf(d2 - a[r][2]) - fabsf(d3 - a[r][3]);
                float n = (pa + qa) - fabsf(d4 - a[r][4]);
                float e = ex2(n);
                accJ[r] += e;
                loc += e;
            }
            if (!diag) {
                loc += __shfl_xor_sync(0xffffffffu, loc, 1);
                loc += __shfl_xor_sync(0xffffffffu, loc, 2);
                if (act && jl == 0)
                    atomicAdd(&out[(ta * TS + ii) * OUT_F + o], loc);
            }
        }

        if (act) {
#pragma unroll
            for (int r = 0; r < 4; r++) {
                float v = accJ[r] - (diag ? 1.0f : 0.0f);
                atomicAdd(&out[(tb * TS + jl + 4 * r) * OUT_F + o], v);
            }
        }
    }
}

extern "C" void kernel_launch(void* const* d_in, const int* in_sizes, int n_in,
                              void* d_out, int out_size) {
    const float* x = (const float*)d_in[0];   // [512, 512]
    const float* T = (const float*)d_in[1];   // [512, 100, 5] -> [512, 500]
    float* out = (float*)d_out;               // [512, 100]

    gemm_kernel<<<dim3(64, 4), 512>>>(x, T, out);
    md_kernel<<<MD_BLOCKS, 416>>>(out);
}